// round 11
// baseline (speedup 1.0000x reference)
#include <cuda_runtime.h>
#include <math.h>
#include <stdint.h>

#define TDEC 250
#define BATCH 128
#define TENC 1024
#define NT 256

__device__ float g_keys[BATCH * TENC * 256];   // enc @ Wk + bk

// ---------------------------------------------------------------- zero wp
__global__ void zero_wp(float* wp) {
    int i = blockIdx.x * blockDim.x + threadIdx.x;
    if (i < TDEC) wp[i] = 0.f;
}

// ------------------------------------------- keys = enc(131072x256) @ Wk + bk
__global__ void keys_gemm(const float* __restrict__ A, const float* __restrict__ B,
                          const float* __restrict__ bias, float* __restrict__ C)
{
    __shared__ float As[16][64], Bs[16][64];
    int tid = threadIdx.x;
    int n0 = blockIdx.x * 64, m0 = blockIdx.y * 64;
    int tm0 = (tid >> 4) * 4, tn0 = (tid & 15) * 4;
    float acc[4][4];
#pragma unroll
    for (int i = 0; i < 4; i++)
#pragma unroll
        for (int j = 0; j < 4; j++) acc[i][j] = 0.f;
    int arow = tid >> 2, akc = (tid & 3) * 4;
    int brow = tid >> 4, bnc = (tid & 15) * 4;
    for (int k0 = 0; k0 < 256; k0 += 16) {
        float4 av = *(const float4*)(A + (size_t)(m0 + arow) * 256 + k0 + akc);
        float4 bv = *(const float4*)(B + (size_t)(k0 + brow) * 256 + n0 + bnc);
        __syncthreads();
        As[akc + 0][arow] = av.x; As[akc + 1][arow] = av.y;
        As[akc + 2][arow] = av.z; As[akc + 3][arow] = av.w;
        *(float4*)&Bs[brow][bnc] = bv;
        __syncthreads();
#pragma unroll
        for (int kk = 0; kk < 16; kk++) {
            float4 a4 = *(float4*)&As[kk][tm0];
            float4 b4 = *(float4*)&Bs[kk][tn0];
            float ar[4] = {a4.x, a4.y, a4.z, a4.w};
            float br[4] = {b4.x, b4.y, b4.z, b4.w};
#pragma unroll
            for (int i = 0; i < 4; i++)
#pragma unroll
                for (int j = 0; j < 4; j++)
                    acc[i][j] = fmaf(ar[i], br[j], acc[i][j]);
        }
    }
#pragma unroll
    for (int i = 0; i < 4; i++) {
        float4 o;
        o.x = acc[i][0] + bias[n0 + tn0 + 0];
        o.y = acc[i][1] + bias[n0 + tn0 + 1];
        o.z = acc[i][2] + bias[n0 + tn0 + 2];
        o.w = acc[i][3] + bias[n0 + tn0 + 3];
        *(float4*)(C + (size_t)(m0 + tm0 + i) * 256 + n0 + tn0) = o;
    }
}

// -------- vec-mat for 2 batch rows: y[r][j] = act(x[r] @ W + b)[j] ----------
// thread handles cols (2*tid, 2*tid+1) via float2 weight loads. Trailing sync.
__device__ __forceinline__ void vm2(const float* __restrict__ W,
                                    const float* __restrict__ bias,
                                    int K, int N,
                                    const float* x0, const float* x1s,
                                    int act, float* y0, float* y1)
{
    int tid = threadIdx.x;
    int jp = tid * 2;
    float r00 = 0.f, r01 = 0.f, r10 = 0.f, r11 = 0.f;
    if (jp < N) {
        const float2* wptr = (const float2*)W + tid;
        int hN = N >> 1;
#pragma unroll 4
        for (int k = 0; k < K; k++) {
            float2 w = wptr[k * hN];
            float a0 = x0[k], a1 = x1s[k];
            r00 = fmaf(a0, w.x, r00); r01 = fmaf(a0, w.y, r01);
            r10 = fmaf(a1, w.x, r10); r11 = fmaf(a1, w.y, r11);
        }
        float bx = bias[jp], by = bias[jp + 1];
        r00 += bx; r01 += by; r10 += bx; r11 += by;
        if (act == 1) {
            r00 = fmaxf(r00, 0.f); r01 = fmaxf(r01, 0.f);
            r10 = fmaxf(r10, 0.f); r11 = fmaxf(r11, 0.f);
        } else if (act == 2) {
            r00 = 1.f / (1.f + expf(-r00)); r01 = 1.f / (1.f + expf(-r01));
            r10 = 1.f / (1.f + expf(-r10)); r11 = 1.f / (1.f + expf(-r11));
        } else if (act == 3) {
            r00 = tanhf(r00); r01 = tanhf(r01);
            r10 = tanhf(r10); r11 = tanhf(r11);
        }
        y0[jp] = r00; y0[jp + 1] = r01;
        y1[jp] = r10; y1[jp + 1] = r11;
    }
    __syncthreads();
}

// ------------------------- persistent decoder: 1 block = 2 batch rows -------
__global__ void __launch_bounds__(NT, 1) decode_kernel(
    const float* __restrict__ enc, const int* __restrict__ mask,
    const float* __restrict__ inp_att, const float* __restrict__ style_tok,
    const float* __restrict__ pre_W1, const float* __restrict__ pre_b1,
    const float* __restrict__ pre_W2, const float* __restrict__ pre_b2,
    const float* __restrict__ att_Wg, const float* __restrict__ att_bg,
    const float* __restrict__ att_Wc, const float* __restrict__ att_bc,
    const float* __restrict__ attn_Wq, const float* __restrict__ attn_bq,
    const float* __restrict__ attn_v,
    const float* __restrict__ deci_W, const float* __restrict__ deci_b,
    const float* __restrict__ dec1_Wg, const float* __restrict__ dec1_bg,
    const float* __restrict__ dec1_Wc, const float* __restrict__ dec1_bc,
    const float* __restrict__ dec2_Wg, const float* __restrict__ dec2_bg,
    const float* __restrict__ dec2_Wc, const float* __restrict__ dec2_bc,
    const float* __restrict__ out_W, const float* __restrict__ out_b,
    float* __restrict__ seq, float* __restrict__ alph, float* __restrict__ wp)
{
    __shared__ float es[2][1024];
    __shared__ float xa[2][640];   // [ctx(256)|p(128)|h or r*h(256)]
    __shared__ float xd[2][512];   // [h_att|wctx]
    __shared__ float x1[2][512];   // [p1 / dec_in / o2 | h1 or r*h1]
    __shared__ float x2[2][512];   // [q / o1 | h2 or r*h2]
    __shared__ float tmp[2][512];
    __shared__ float hA[2][256], h1s[2][256], h2s[2][256], us[2][256], sst[2][256];
    __shared__ float lastv[2][80];
    __shared__ float vsh[256];
    __shared__ float red[2][8];

    const int tid = threadIdx.x;
    const int blk = blockIdx.x;

    vsh[tid] = attn_v[tid];
#pragma unroll
    for (int r = 0; r < 2; r++) {
        int b = blk * 2 + r;
        float s = 0.f;
#pragma unroll
        for (int k = 0; k < 10; k++)
            s += inp_att[b * 10 + k] * style_tok[k * 256 + tid];
        sst[r][tid] = s;
        hA[r][tid] = 0.f; h1s[r][tid] = 0.f; h2s[r][tid] = 0.f;
        xa[r][tid] = 0.f;                       // ctx = 0
        if (tid < 80) lastv[r][tid] = 0.f;
    }
    __syncthreads();

    const int mb0 = mask[blk * 2], mb1 = mask[blk * 2 + 1];
    const int lane = tid & 31;
    const int rr = tid >> 7;                    // attention row (0/1)
    const int wl = (tid >> 5) & 3;              // warp-within-row
    const int lt = tid & 127;
    const int mbr = rr ? mb1 : mb0;
    const size_t browg = (size_t)(blk * 2 + rr);

    for (int t = 0; t < TDEC; t++) {
        // S1: p1 = relu(last @ W1 + b1) -> x1[:256)
        vm2(pre_W1, pre_b1, 80, 256, lastv[0], lastv[1], 1, x1[0], x1[1]);
        // S2: p = relu(p1 @ W2 + b2) -> xa[256:384)
        vm2(pre_W2, pre_b2, 256, 128, x1[0], x1[1], 1, xa[0] + 256, xa[1] + 256);
        // copy h_att -> xa[384:640)
        xa[0][384 + tid] = hA[0][tid];
        xa[1][384 + tid] = hA[1][tid];
        __syncthreads();
        // S3: gates = sigmoid([ctx,p,h] @ att_Wg + bg)
        vm2(att_Wg, att_bg, 640, 512, xa[0], xa[1], 2, tmp[0], tmp[1]);
        xa[0][384 + tid] = tmp[0][tid] * hA[0][tid]; us[0][tid] = tmp[0][256 + tid];
        xa[1][384 + tid] = tmp[1][tid] * hA[1][tid]; us[1][tid] = tmp[1][256 + tid];
        __syncthreads();
        // S4: c = tanh([ctx,p,r*h] @ att_Wc + bc); h_att = u*h + (1-u)*c
        vm2(att_Wc, att_bc, 640, 256, xa[0], xa[1], 3, tmp[0], tmp[1]);
#pragma unroll
        for (int r = 0; r < 2; r++) {
            float u = us[r][tid];
            float hn = u * hA[r][tid] + (1.f - u) * tmp[r][tid];
            hA[r][tid] = hn;
            xd[r][tid] = hn;
        }
        __syncthreads();
        // S5: q = h_att @ Wq + bq -> x2[:256)
        vm2(attn_Wq, attn_bq, 256, 256, hA[0], hA[1], 0, x2[0], x2[1]);

        // ---- S6: attention ----
        {
            const float4* qv = (const float4*)x2[rr];
            float4 q0 = qv[lane], q1 = qv[32 + lane];
            const float4* vv = (const float4*)vsh;
            float4 v0 = vv[lane], v1 = vv[32 + lane];
            const float* kbase = g_keys + browg * TENC * 256;
            for (int tt = wl; tt < mbr; tt += 4) {
                const float4* kp = (const float4*)(kbase + (size_t)tt * 256);
                float4 k0 = kp[lane], k1 = kp[32 + lane];
                float part;
                part  = tanhf(k0.x + q0.x) * v0.x;
                part += tanhf(k0.y + q0.y) * v0.y;
                part += tanhf(k0.z + q0.z) * v0.z;
                part += tanhf(k0.w + q0.w) * v0.w;
                part += tanhf(k1.x + q1.x) * v1.x;
                part += tanhf(k1.y + q1.y) * v1.y;
                part += tanhf(k1.z + q1.z) * v1.z;
                part += tanhf(k1.w + q1.w) * v1.w;
#pragma unroll
                for (int o = 16; o; o >>= 1)
                    part += __shfl_xor_sync(0xffffffffu, part, o);
                if (lane == 0) es[rr][tt] = part;
            }
            __syncthreads();
            // softmax over [0, mbr) with 128 threads per row
            float mx = -1e30f;
            for (int tt = lt; tt < mbr; tt += 128) mx = fmaxf(mx, es[rr][tt]);
#pragma unroll
            for (int o = 16; o; o >>= 1)
                mx = fmaxf(mx, __shfl_xor_sync(0xffffffffu, mx, o));
            if (lane == 0) red[rr][wl] = mx;
            __syncthreads();
            mx = fmaxf(fmaxf(red[rr][0], red[rr][1]), fmaxf(red[rr][2], red[rr][3]));
            float sm = 0.f;
            for (int tt = lt; tt < mbr; tt += 128) {
                float p = expf(es[rr][tt] - mx);
                es[rr][tt] = p;
                sm += p;
            }
#pragma unroll
            for (int o = 16; o; o >>= 1)
                sm += __shfl_xor_sync(0xffffffffu, sm, o);
            __syncthreads();
            if (lane == 0) red[rr][wl] = sm;
            __syncthreads();
            float inv = 1.f / (red[rr][0] + red[rr][1] + red[rr][2] + red[rr][3]);
            float* arow = alph + ((size_t)t * BATCH + browg) * 1024;
            for (int tt = lt; tt < 1024; tt += 128) {
                float a = (tt < mbr) ? es[rr][tt] * inv : 0.f;
                es[rr][tt] = a;
                arow[tt] = a;
            }
            __syncthreads();
            // context
            const float* erow = enc + browg * TENC * 256;
            float c0 = 0.f, c1 = 0.f;
#pragma unroll 4
            for (int tt = 0; tt < mbr; tt++) {
                float a = es[rr][tt];
                c0 = fmaf(a, erow[(size_t)tt * 256 + lt], c0);
                c1 = fmaf(a, erow[(size_t)tt * 256 + 128 + lt], c1);
            }
            xa[rr][lt] = c0; xa[rr][128 + lt] = c1;          // ctx carry
            xd[rr][256 + lt] = c0 + sst[rr][lt];             // wctx
            xd[rr][256 + 128 + lt] = c1 + sst[rr][128 + lt];
            float a0 = fabsf(sst[rr][lt]), a1 = fabsf(sst[rr][128 + lt]);
            float f = a0 / (fabsf(c0) + a0) + a1 / (fabsf(c1) + a1);
#pragma unroll
            for (int o = 16; o; o >>= 1)
                f += __shfl_xor_sync(0xffffffffu, f, o);
            __syncthreads();
            if (lane == 0) red[rr][wl] = f;
            __syncthreads();
            if (tid == 0) {
                float s = red[0][0] + red[0][1] + red[0][2] + red[0][3]
                        + red[1][0] + red[1][1] + red[1][2] + red[1][3];
                atomicAdd(wp + t, s * (1.f / (BATCH * 256.f)));
            }
            __syncthreads();
        }

        // S7: dec_in = [h_att, wctx] @ deci_W + b -> x1[:256)
        vm2(deci_W, deci_b, 512, 256, xd[0], xd[1], 0, x1[0], x1[1]);
        // copy h1 -> x1[256:512)
        x1[0][256 + tid] = h1s[0][tid];
        x1[1][256 + tid] = h1s[1][tid];
        __syncthreads();
        // S8: dec1 gates
        vm2(dec1_Wg, dec1_bg, 512, 512, x1[0], x1[1], 2, tmp[0], tmp[1]);
        x1[0][256 + tid] = tmp[0][tid] * h1s[0][tid]; us[0][tid] = tmp[0][256 + tid];
        x1[1][256 + tid] = tmp[1][tid] * h1s[1][tid]; us[1][tid] = tmp[1][256 + tid];
        __syncthreads();
        // S9: dec1 cand; h1 update; o1 = h1 + dec_in -> x2[:256)
        vm2(dec1_Wc, dec1_bc, 512, 256, x1[0], x1[1], 3, tmp[0], tmp[1]);
#pragma unroll
        for (int r = 0; r < 2; r++) {
            float u = us[r][tid];
            float hn = u * h1s[r][tid] + (1.f - u) * tmp[r][tid];
            h1s[r][tid] = hn;
            x2[r][tid] = hn + x1[r][tid];
        }
        __syncthreads();
        // copy h2 -> x2[256:512)
        x2[0][256 + tid] = h2s[0][tid];
        x2[1][256 + tid] = h2s[1][tid];
        __syncthreads();
        // S10: dec2 gates
        vm2(dec2_Wg, dec2_bg, 512, 512, x2[0], x2[1], 2, tmp[0], tmp[1]);
        x2[0][256 + tid] = tmp[0][tid] * h2s[0][tid]; us[0][tid] = tmp[0][256 + tid];
        x2[1][256 + tid] = tmp[1][tid] * h2s[1][tid]; us[1][tid] = tmp[1][256 + tid];
        __syncthreads();
        // S11: dec2 cand; h2 update; o2 = h2 + o1 -> x1[:256)
        vm2(dec2_Wc, dec2_bc, 512, 256, x2[0], x2[1], 3, tmp[0], tmp[1]);
#pragma unroll
        for (int r = 0; r < 2; r++) {
            float u = us[r][tid];
            float hn = u * h2s[r][tid] + (1.f - u) * tmp[r][tid];
            h2s[r][tid] = hn;
            x1[r][tid] = hn + x2[r][tid];
        }
        __syncthreads();
        // S12: dense_out = o2 @ out_W + out_b (N=400)
        vm2(out_W, out_b, 256, 400, x1[0], x1[1], 0, tmp[0], tmp[1]);
#pragma unroll
        for (int rep = 0; rep < 2; rep++) {
            int j = tid + rep * 256;
            if (j < 400) {
#pragma unroll
                for (int r = 0; r < 2; r++) {
                    float v = tmp[r][j];
                    seq[(size_t)(blk * 2 + r) * (TDEC * 400) + t * 400 + j] = v;
                    if (j >= 320) lastv[r][j - 320] = v;
                }
            }
        }
        __syncthreads();
    }
}

extern "C" void kernel_launch(void* const* d_in, const int* in_sizes, int n_in,
                              void* d_out, int out_size)
{
    const float* enc      = (const float*)d_in[0];
    const int*   mask     = (const int*)d_in[1];
    const float* inp_att  = (const float*)d_in[2];
    const float* style_tk = (const float*)d_in[3];
    const float* pre_W1   = (const float*)d_in[4];
    const float* pre_b1   = (const float*)d_in[5];
    const float* pre_W2   = (const float*)d_in[6];
    const float* pre_b2   = (const float*)d_in[7];
    const float* att_Wg   = (const float*)d_in[8];
    const float* att_bg   = (const float*)d_in[9];
    const float* att_Wc   = (const float*)d_in[10];
    const float* att_bc   = (const float*)d_in[11];
    const float* attn_Wk  = (const float*)d_in[12];
    const float* attn_bk  = (const float*)d_in[13];
    const float* attn_Wq  = (const float*)d_in[14];
    const float* attn_bq  = (const float*)d_in[15];
    const float* attn_v   = (const float*)d_in[16];
    const float* deci_W   = (const float*)d_in[17];
    const float* deci_b   = (const float*)d_in[18];
    const float* dec1_Wg  = (const float*)d_in[19];
    const float* dec1_bg  = (const float*)d_in[20];
    const float* dec1_Wc  = (const float*)d_in[21];
    const float* dec1_bc  = (const float*)d_in[22];
    const float* dec2_Wg  = (const float*)d_in[23];
    const float* dec2_bg  = (const float*)d_in[24];
    const float* dec2_Wc  = (const float*)d_in[25];
    const float* dec2_bc  = (const float*)d_in[26];
    const float* out_W    = (const float*)d_in[27];
    const float* out_b    = (const float*)d_in[28];

    float* out  = (float*)d_out;
    float* seq  = out;                                   // 128*1250*80
    float* alph = out + (size_t)BATCH * TDEC * 5 * 80;   // 250*128*1024
    float* wp   = alph + (size_t)TDEC * BATCH * TENC;    // 250

    float* pKeys;
    cudaGetSymbolAddress((void**)&pKeys, g_keys);

    zero_wp<<<1, 256>>>(wp);
    keys_gemm<<<dim3(4, 2048), 256>>>(enc, attn_Wk, attn_bk, pKeys);
    decode_kernel<<<BATCH / 2, NT>>>(
        enc, mask, inp_att, style_tk,
        pre_W1, pre_b1, pre_W2, pre_b2,
        att_Wg, att_bg, att_Wc, att_bc,
        attn_Wq, attn_bq, attn_v,
        deci_W, deci_b,
        dec1_Wg, dec1_bg, dec1_Wc, dec1_bc,
        dec2_Wg, dec2_bg, dec2_Wc, dec2_bc,
        out_W, out_b,
        seq, alph, wp);
}

// round 12
// speedup vs baseline: 2.6650x; 2.6650x over previous
#include <cuda_runtime.h>
#include <cuda_bf16.h>
#include <math.h>
#include <stdint.h>

#define TDEC 250
#define BATCH 128
#define TENC 1024
#define NT 512

__device__ __nv_bfloat16 g_keys[BATCH * TENC * 256];   // enc @ Wk + bk (bf16)

__device__ __forceinline__ float tanh_fast(float x) {
    float y;
    asm("tanh.approx.f32 %0, %1;" : "=f"(y) : "f"(x));
    return y;
}

// ---------------------------------------------------------------- zero wp
__global__ void zero_wp(float* wp) {
    int i = blockIdx.x * blockDim.x + threadIdx.x;
    if (i < TDEC) wp[i] = 0.f;
}

// ---------------- keys = enc(131072x256) @ Wk + bk  -> bf16 ----------------
__global__ void keys_gemm(const float* __restrict__ A, const float* __restrict__ B,
                          const float* __restrict__ bias, __nv_bfloat16* __restrict__ C)
{
    __shared__ float As[16][64], Bs[16][64];
    int tid = threadIdx.x;
    int n0 = blockIdx.x * 64, m0 = blockIdx.y * 64;
    int tm0 = (tid >> 4) * 4, tn0 = (tid & 15) * 4;
    float acc[4][4];
#pragma unroll
    for (int i = 0; i < 4; i++)
#pragma unroll
        for (int j = 0; j < 4; j++) acc[i][j] = 0.f;
    int arow = tid >> 2, akc = (tid & 3) * 4;
    int brow = tid >> 4, bnc = (tid & 15) * 4;
    for (int k0 = 0; k0 < 256; k0 += 16) {
        float4 av = *(const float4*)(A + (size_t)(m0 + arow) * 256 + k0 + akc);
        float4 bv = *(const float4*)(B + (size_t)(k0 + brow) * 256 + n0 + bnc);
        __syncthreads();
        As[akc + 0][arow] = av.x; As[akc + 1][arow] = av.y;
        As[akc + 2][arow] = av.z; As[akc + 3][arow] = av.w;
        *(float4*)&Bs[brow][bnc] = bv;
        __syncthreads();
#pragma unroll
        for (int kk = 0; kk < 16; kk++) {
            float4 a4 = *(float4*)&As[kk][tm0];
            float4 b4 = *(float4*)&Bs[kk][tn0];
            float ar[4] = {a4.x, a4.y, a4.z, a4.w};
            float br[4] = {b4.x, b4.y, b4.z, b4.w};
#pragma unroll
            for (int i = 0; i < 4; i++)
#pragma unroll
                for (int j = 0; j < 4; j++)
                    acc[i][j] = fmaf(ar[i], br[j], acc[i][j]);
        }
    }
#pragma unroll
    for (int i = 0; i < 4; i++) {
        float x0 = acc[i][0] + bias[n0 + tn0 + 0];
        float x1 = acc[i][1] + bias[n0 + tn0 + 1];
        float x2 = acc[i][2] + bias[n0 + tn0 + 2];
        float x3 = acc[i][3] + bias[n0 + tn0 + 3];
        __nv_bfloat162 p0 = __floats2bfloat162_rn(x0, x1);
        __nv_bfloat162 p1 = __floats2bfloat162_rn(x2, x3);
        uint2 pk;
        pk.x = *(uint32_t*)&p0;
        pk.y = *(uint32_t*)&p1;
        *(uint2*)(C + (size_t)(m0 + tm0 + i) * 256 + n0 + tn0) = pk;
    }
}

// --- vec-mat, 2 rows: thread owns column j=tid; float4 LDS x, unroll-4 W ---
__device__ __forceinline__ void vm(const float* __restrict__ W,
                                   const float* __restrict__ bias,
                                   int K, int N,
                                   const float* x0, const float* x1,
                                   int act, float* y0, float* y1)
{
    int j = threadIdx.x;
    if (j < N) {
        float r0 = 0.f, r1 = 0.f;
        const float4* a0 = (const float4*)x0;
        const float4* a1 = (const float4*)x1;
        const float* wp = W + j;
        int K4 = K >> 2;
#pragma unroll 4
        for (int k4 = 0; k4 < K4; k4++) {
            float4 xa = a0[k4];
            float4 xb = a1[k4];
            const float* wk = wp + (size_t)k4 * 4 * N;
            float w0 = wk[0];
            float w1 = wk[N];
            float w2 = wk[2 * N];
            float w3 = wk[3 * N];
            r0 = fmaf(xa.x, w0, r0); r1 = fmaf(xb.x, w0, r1);
            r0 = fmaf(xa.y, w1, r0); r1 = fmaf(xb.y, w1, r1);
            r0 = fmaf(xa.z, w2, r0); r1 = fmaf(xb.z, w2, r1);
            r0 = fmaf(xa.w, w3, r0); r1 = fmaf(xb.w, w3, r1);
        }
        float bv = bias[j];
        r0 += bv; r1 += bv;
        if (act == 1) { r0 = fmaxf(r0, 0.f); r1 = fmaxf(r1, 0.f); }
        else if (act == 2) {
            r0 = 1.f / (1.f + expf(-r0));
            r1 = 1.f / (1.f + expf(-r1));
        } else if (act == 3) { r0 = tanhf(r0); r1 = tanhf(r1); }
        y0[j] = r0; y1[j] = r1;
    }
    __syncthreads();
}

// ------------------- persistent decoder: 1 block = 2 batch rows ------------
__global__ void __launch_bounds__(NT, 1) decode_kernel(
    const float* __restrict__ enc, const int* __restrict__ mask,
    const float* __restrict__ inp_att, const float* __restrict__ style_tok,
    const float* __restrict__ pre_W1, const float* __restrict__ pre_b1,
    const float* __restrict__ pre_W2, const float* __restrict__ pre_b2,
    const float* __restrict__ att_Wg, const float* __restrict__ att_bg,
    const float* __restrict__ att_Wc, const float* __restrict__ att_bc,
    const float* __restrict__ attn_Wq, const float* __restrict__ attn_bq,
    const float* __restrict__ attn_v,
    const float* __restrict__ deci_W, const float* __restrict__ deci_b,
    const float* __restrict__ dec1_Wg, const float* __restrict__ dec1_bg,
    const float* __restrict__ dec1_Wc, const float* __restrict__ dec1_bc,
    const float* __restrict__ dec2_Wg, const float* __restrict__ dec2_bg,
    const float* __restrict__ dec2_Wc, const float* __restrict__ dec2_bc,
    const float* __restrict__ out_W, const float* __restrict__ out_b,
    float* __restrict__ seq, float* __restrict__ alph, float* __restrict__ wp)
{
    __shared__ float es[2][1024];
    __shared__ float xa[2][640];   // [ctx(256)|p(128)|h or r*h(256)]
    __shared__ float xd[2][512];   // [h_att|wctx]
    __shared__ float x1[2][512];   // p1 / dec_in / o2 ...
    __shared__ float x2[2][512];   // q / o1 ...
    __shared__ float tmp[2][512];
    __shared__ float hA[2][256], h1s[2][256], h2s[2][256], us[2][256], sst[2][256];
    __shared__ float lastv[2][80];
    __shared__ float vsh[256];
    __shared__ float red[2][8];

    const int tid = threadIdx.x;
    const int blk = blockIdx.x;
    const int r8 = tid >> 8;        // row index for 2x256 ops
    const int d8 = tid & 255;       // dim within row

    if (tid < 256) vsh[tid] = attn_v[tid];
    {
        int b = blk * 2 + r8;
        float s = 0.f;
#pragma unroll
        for (int k = 0; k < 10; k++)
            s += inp_att[b * 10 + k] * style_tok[k * 256 + d8];
        sst[r8][d8] = s;
        hA[r8][d8] = 0.f; h1s[r8][d8] = 0.f; h2s[r8][d8] = 0.f;
        xa[r8][d8] = 0.f;                       // ctx = 0
        if (d8 < 80) lastv[r8][d8] = 0.f;
    }
    __syncthreads();

    const int mb0 = mask[blk * 2], mb1 = mask[blk * 2 + 1];
    const int lane = tid & 31;
    const int rr = tid >> 8;                    // attention row (0/1)
    const int wl = (tid >> 5) & 7;              // warp-within-row (0..7)
    const int lt = tid & 255;                   // thread-within-row (0..255)
    const int mbr = rr ? mb1 : mb0;
    const size_t browg = (size_t)(blk * 2 + rr);

    for (int t = 0; t < TDEC; t++) {
        // S1: p1 = relu(last @ W1 + b1) -> x1[:256)
        vm(pre_W1, pre_b1, 80, 256, lastv[0], lastv[1], 1, x1[0], x1[1]);
        // S2: p = relu(p1 @ W2 + b2) -> xa[256:384)
        vm(pre_W2, pre_b2, 256, 128, x1[0], x1[1], 1, xa[0] + 256, xa[1] + 256);
        // h_att -> xa[384:640)
        xa[r8][384 + d8] = hA[r8][d8];
        __syncthreads();
        // S3: gates = sigmoid([ctx,p,h] @ att_Wg + bg)
        vm(att_Wg, att_bg, 640, 512, xa[0], xa[1], 2, tmp[0], tmp[1]);
        xa[r8][384 + d8] = tmp[r8][d8] * hA[r8][d8];
        us[r8][d8] = tmp[r8][256 + d8];
        __syncthreads();
        // S4: c = tanh([ctx,p,r*h] @ att_Wc + bc); h_att = u*h + (1-u)*c
        vm(att_Wc, att_bc, 640, 256, xa[0], xa[1], 3, tmp[0], tmp[1]);
        {
            float u = us[r8][d8];
            float hn = u * hA[r8][d8] + (1.f - u) * tmp[r8][d8];
            hA[r8][d8] = hn;
            xd[r8][d8] = hn;
        }
        __syncthreads();
        // S5: q = h_att @ Wq + bq -> x2[:256)
        vm(attn_Wq, attn_bq, 256, 256, hA[0], hA[1], 0, x2[0], x2[1]);

        // ---- S6: attention (8 warps per row) ----
        {
            const int d0 = lane * 8;
            const float* qs = x2[rr];
            float4 qa = *(const float4*)&qs[d0];
            float4 qb = *(const float4*)&qs[d0 + 4];
            float4 va = *(const float4*)&vsh[d0];
            float4 vb = *(const float4*)&vsh[d0 + 4];
            const __nv_bfloat16* kbase = g_keys + browg * TENC * 256;
            for (int tt = wl; tt < mbr; tt += 8) {
                uint4 kv = *(const uint4*)(kbase + (size_t)tt * 256 + d0);
                float2 f0 = __bfloat1622float2(*(__nv_bfloat162*)&kv.x);
                float2 f1 = __bfloat1622float2(*(__nv_bfloat162*)&kv.y);
                float2 f2 = __bfloat1622float2(*(__nv_bfloat162*)&kv.z);
                float2 f3 = __bfloat1622float2(*(__nv_bfloat162*)&kv.w);
                float part;
                part  = tanh_fast(f0.x + qa.x) * va.x;
                part += tanh_fast(f0.y + qa.y) * va.y;
                part += tanh_fast(f1.x + qa.z) * va.z;
                part += tanh_fast(f1.y + qa.w) * va.w;
                part += tanh_fast(f2.x + qb.x) * vb.x;
                part += tanh_fast(f2.y + qb.y) * vb.y;
                part += tanh_fast(f3.x + qb.z) * vb.z;
                part += tanh_fast(f3.y + qb.w) * vb.w;
#pragma unroll
                for (int o = 16; o; o >>= 1)
                    part += __shfl_xor_sync(0xffffffffu, part, o);
                if (lane == 0) es[rr][tt] = part;
            }
            __syncthreads();
            // softmax over [0, mbr), 256 threads per row
            float mx = -1e30f;
            for (int tt = lt; tt < mbr; tt += 256) mx = fmaxf(mx, es[rr][tt]);
#pragma unroll
            for (int o = 16; o; o >>= 1)
                mx = fmaxf(mx, __shfl_xor_sync(0xffffffffu, mx, o));
            if (lane == 0) red[rr][wl] = mx;
            __syncthreads();
            mx = red[rr][0];
#pragma unroll
            for (int i = 1; i < 8; i++) mx = fmaxf(mx, red[rr][i]);
            float sm = 0.f;
            for (int tt = lt; tt < mbr; tt += 256) {
                float p = __expf(es[rr][tt] - mx);
                es[rr][tt] = p;
                sm += p;
            }
#pragma unroll
            for (int o = 16; o; o >>= 1)
                sm += __shfl_xor_sync(0xffffffffu, sm, o);
            __syncthreads();
            if (lane == 0) red[rr][wl] = sm;
            __syncthreads();
            float tsum = red[rr][0];
#pragma unroll
            for (int i = 1; i < 8; i++) tsum += red[rr][i];
            float inv = 1.f / tsum;
            float* arow = alph + ((size_t)t * BATCH + browg) * 1024;
            for (int tt = lt; tt < 1024; tt += 256) {
                float a = (tt < mbr) ? es[rr][tt] * inv : 0.f;
                es[rr][tt] = a;
                arow[tt] = a;
            }
            __syncthreads();
            // context: thread lt owns dim lt
            const float* erow = enc + browg * TENC * 256 + lt;
            float c = 0.f;
#pragma unroll 8
            for (int tt = 0; tt < mbr; tt++)
                c = fmaf(es[rr][tt], erow[(size_t)tt * 256], c);
            xa[rr][lt] = c;                       // ctx carry
            xd[rr][256 + lt] = c + sst[rr][lt];   // wctx
            float as_ = fabsf(sst[rr][lt]);
            float f = as_ / (fabsf(c) + as_);
#pragma unroll
            for (int o = 16; o; o >>= 1)
                f += __shfl_xor_sync(0xffffffffu, f, o);
            __syncthreads();
            if (lane == 0) red[rr][wl] = f;
            __syncthreads();
            if (tid == 0) {
                float s = 0.f;
#pragma unroll
                for (int i = 0; i < 8; i++) s += red[0][i] + red[1][i];
                atomicAdd(wp + t, s * (1.f / (BATCH * 256.f)));
            }
            __syncthreads();
        }

        // S7: dec_in = [h_att, wctx] @ deci_W + b -> x1[:256)
        vm(deci_W, deci_b, 512, 256, xd[0], xd[1], 0, x1[0], x1[1]);
        x1[r8][256 + d8] = h1s[r8][d8];
        __syncthreads();
        // S8: dec1 gates
        vm(dec1_Wg, dec1_bg, 512, 512, x1[0], x1[1], 2, tmp[0], tmp[1]);
        x1[r8][256 + d8] = tmp[r8][d8] * h1s[r8][d8];
        us[r8][d8] = tmp[r8][256 + d8];
        __syncthreads();
        // S9: dec1 cand; h1 update; o1 = h1 + dec_in -> x2[:256)
        vm(dec1_Wc, dec1_bc, 512, 256, x1[0], x1[1], 3, tmp[0], tmp[1]);
        {
            float u = us[r8][d8];
            float hn = u * h1s[r8][d8] + (1.f - u) * tmp[r8][d8];
            h1s[r8][d8] = hn;
            x2[r8][d8] = hn + x1[r8][d8];
            x2[r8][256 + d8] = h2s[r8][d8];
        }
        __syncthreads();
        // S10: dec2 gates
        vm(dec2_Wg, dec2_bg, 512, 512, x2[0], x2[1], 2, tmp[0], tmp[1]);
        x2[r8][256 + d8] = tmp[r8][d8] * h2s[r8][d8];
        us[r8][d8] = tmp[r8][256 + d8];
        __syncthreads();
        // S11: dec2 cand; h2 update; o2 = h2 + o1 -> x1[:256)
        vm(dec2_Wc, dec2_bc, 512, 256, x2[0], x2[1], 3, tmp[0], tmp[1]);
        {
            float u = us[r8][d8];
            float hn = u * h2s[r8][d8] + (1.f - u) * tmp[r8][d8];
            h2s[r8][d8] = hn;
            x1[r8][d8] = hn + x2[r8][d8];
        }
        __syncthreads();
        // S12: dense_out = o2 @ out_W + out_b (N=400)
        vm(out_W, out_b, 256, 400, x1[0], x1[1], 0, tmp[0], tmp[1]);
        if (tid < 400) {
#pragma unroll
            for (int r = 0; r < 2; r++) {
                float v = tmp[r][tid];
                seq[(size_t)(blk * 2 + r) * (TDEC * 400) + t * 400 + tid] = v;
                if (tid >= 320) lastv[r][tid - 320] = v;
            }
        }
        __syncthreads();
    }
}

extern "C" void kernel_launch(void* const* d_in, const int* in_sizes, int n_in,
                              void* d_out, int out_size)
{
    const float* enc      = (const float*)d_in[0];
    const int*   mask     = (const int*)d_in[1];
    const float* inp_att  = (const float*)d_in[2];
    const float* style_tk = (const float*)d_in[3];
    const float* pre_W1   = (const float*)d_in[4];
    const float* pre_b1   = (const float*)d_in[5];
    const float* pre_W2   = (const float*)d_in[6];
    const float* pre_b2   = (const float*)d_in[7];
    const float* att_Wg   = (const float*)d_in[8];
    const float* att_bg   = (const float*)d_in[9];
    const float* att_Wc   = (const float*)d_in[10];
    const float* att_bc   = (const float*)d_in[11];
    const float* attn_Wk  = (const float*)d_in[12];
    const float* attn_bk  = (const float*)d_in[13];
    const float* attn_Wq  = (const float*)d_in[14];
    const float* attn_bq  = (const float*)d_in[15];
    const float* attn_v   = (const float*)d_in[16];
    const float* deci_W   = (const float*)d_in[17];
    const float* deci_b   = (const float*)d_in[18];
    const float* dec1_Wg  = (const float*)d_in[19];
    const float* dec1_bg  = (const float*)d_in[20];
    const float* dec1_Wc  = (const float*)d_in[21];
    const float* dec1_bc  = (const float*)d_in[22];
    const float* dec2_Wg  = (const float*)d_in[23];
    const float* dec2_bg  = (const float*)d_in[24];
    const float* dec2_Wc  = (const float*)d_in[25];
    const float* dec2_bc  = (const float*)d_in[26];
    const float* out_W    = (const float*)d_in[27];
    const float* out_b    = (const float*)d_in[28];

    float* out  = (float*)d_out;
    float* seq  = out;                                   // 128*1250*80
    float* alph = out + (size_t)BATCH * TDEC * 5 * 80;   // 250*128*1024
    float* wp   = alph + (size_t)TDEC * BATCH * TENC;    // 250

    __nv_bfloat16* pKeys;
    cudaGetSymbolAddress((void**)&pKeys, g_keys);

    zero_wp<<<1, 256>>>(wp);
    keys_gemm<<<dim3(4, 2048), 256>>>(enc, attn_Wk, attn_bk, pKeys);
    decode_kernel<<<BATCH / 2, NT>>>(
        enc, mask, inp_att, style_tk,
        pre_W1, pre_b1, pre_W2, pre_b2,
        att_Wg, att_bg, att_Wc, att_bc,
        attn_Wq, attn_bq, attn_v,
        deci_W, deci_b,
        dec1_Wg, dec1_bg, dec1_Wc, dec1_bc,
        dec2_Wg, dec2_bg, dec2_Wc, dec2_bc,
        out_W, out_b,
        seq, alph, wp);
}